// round 12
// baseline (speedup 1.0000x reference)
#include <cuda_runtime.h>
#include <math.h>

#define H   256
#define K1  16
#define K2  32
#define KK  48
#define NC  7
#define MAXB 14000
#define EPSF 1e-8f

typedef unsigned long long u64;

// Scratch (allocation-free rule: device globals). Zero-initialized at load;
// k2 restores g_classSums/g_counts to zero each launch so graph replays are
// self-consistent.
__device__ float g_rawret[(size_t)MAXB * H];
__device__ float g_classSums[NC * H];
__device__ int   g_counts[NC];
__device__ float g_avescaled[NC * H];

// ---- packed f32x2 helpers (ptxas won't emit FFMA2 from C++) ----
__device__ __forceinline__ u64 fma2(u64 a, u64 b, u64 c) {
    u64 d;
    asm("fma.rn.f32x2 %0, %1, %2, %3;" : "=l"(d) : "l"(a), "l"(b), "l"(c));
    return d;
}
__device__ __forceinline__ u64 mul2(u64 a, u64 b) {
    u64 d;
    asm("mul.rn.f32x2 %0, %1, %2;" : "=l"(d) : "l"(a), "l"(b));
    return d;
}
__device__ __forceinline__ u64 pk2(float lo, float hi) {
    u64 r;
    asm("mov.b64 %0, {%1, %2};" : "=l"(r) : "f"(lo), "f"(hi));
    return r;
}
__device__ __forceinline__ float2 upk2(u64 v) {
    float2 r;
    asm("mov.b64 {%0, %1}, %2;" : "=f"(r.x), "=f"(r.y) : "l"(v));
    return r;
}
__device__ __forceinline__ float hsum2(u64 v) {
    const float2 f = upk2(v);
    return f.x + f.y;
}
__device__ __forceinline__ float d4(float4 a, float4 b) {
    return a.x * b.x + a.y * b.y + a.z * b.z + a.w * b.w;
}

// ---------------------------------------------------------------------------
// Streamed hop accumulation: process nk neighbors (2 per group) of one hop.
// For each neighbor: wv = w ⊙ v (in place), d = Σ cs·wv, q = Σ wv², fold the
// 4 values {d0,q0,d1,q1} across lanes (lane l ends with total of val[l&3]),
// e = exp(d·rcn/max(√q,eps)) on lanes l&3∈{0,2}, broadcast, then
// acc += e·wv (the hop-scaled neighbor — no end-scaling needed), den += e.
// ---------------------------------------------------------------------------
__device__ __forceinline__ void hop_accum(
    const float* __restrict__ embeds, const int* __restrict__ nbr, int nk,
    ulonglong2 wa, ulonglong2 wb, ulonglong2 cpa, ulonglong2 cpb,
    float rcn, int lane,
    u64& ax, u64& ay, u64& bx, u64& by, float& den)
{
    const unsigned FULL = 0xffffffffu;
    for (int g = 0; g < nk / 2; g++) {
        const int2 rows = *(const int2*)(nbr + 2 * g);   // broadcast, L1-hot
        const ulonglong2* r0 = (const ulonglong2*)(embeds + (size_t)rows.x * H);
        const ulonglong2* r1 = (const ulonglong2*)(embeds + (size_t)rows.y * H);
        ulonglong2 p0a = r0[lane], p0b = r0[32 + lane];
        ulonglong2 p1a = r1[lane], p1b = r1[32 + lane];

        // wv in place
        p0a.x = mul2(p0a.x, wa.x);  p0a.y = mul2(p0a.y, wa.y);
        p0b.x = mul2(p0b.x, wb.x);  p0b.y = mul2(p0b.y, wb.y);
        p1a.x = mul2(p1a.x, wa.x);  p1a.y = mul2(p1a.y, wa.y);
        p1b.x = mul2(p1b.x, wb.x);  p1b.y = mul2(p1b.y, wb.y);

        float val[4];
        val[0] = hsum2(fma2(cpa.x, p0a.x, fma2(cpa.y, p0a.y,
                       fma2(cpb.x, p0b.x, mul2(cpb.y, p0b.y)))));
        val[1] = hsum2(fma2(p0a.x, p0a.x, fma2(p0a.y, p0a.y,
                       fma2(p0b.x, p0b.x, mul2(p0b.y, p0b.y)))));
        val[2] = hsum2(fma2(cpa.x, p1a.x, fma2(cpa.y, p1a.y,
                       fma2(cpb.x, p1b.x, mul2(cpb.y, p1b.y)))));
        val[3] = hsum2(fma2(p1a.x, p1a.x, fma2(p1a.y, p1a.y,
                       fma2(p1b.x, p1b.x, mul2(p1b.y, p1b.y)))));

        // 4-value interleaved folding butterfly
        float r[2];
        #pragma unroll
        for (int j = 0; j < 2; j++) {
            const float send = (lane & 1) ? val[2 * j] : val[2 * j + 1];
            const float recv = __shfl_xor_sync(FULL, send, 1);
            const float keep = (lane & 1) ? val[2 * j + 1] : val[2 * j];
            r[j] = keep + recv;
        }
        float s;
        {
            const float send = (lane & 2) ? r[0] : r[1];
            const float recv = __shfl_xor_sync(FULL, send, 2);
            const float keep = (lane & 2) ? r[1] : r[0];
            s = keep + recv;
        }
        s += __shfl_xor_sync(FULL, s, 4);
        s += __shfl_xor_sync(FULL, s, 8);
        s += __shfl_xor_sync(FULL, s, 16);
        // lane l holds total of val[l&3]; pair d with q
        const float qn = __shfl_xor_sync(FULL, s, 1);
        const float e  = __expf(s * rcn / fmaxf(sqrtf(qn), EPSF));
        const float e0 = __shfl_sync(FULL, e, 0);
        const float e1 = __shfl_sync(FULL, e, 2);
        den += e0 + e1;

        const u64 ep0 = pk2(e0, e0);
        const u64 ep1 = pk2(e1, e1);
        ax = fma2(ep0, p0a.x, ax);  ax = fma2(ep1, p1a.x, ax);
        ay = fma2(ep0, p0a.y, ay);  ay = fma2(ep1, p1a.y, ay);
        bx = fma2(ep0, p0b.x, bx);  bx = fma2(ep1, p1b.x, bx);
        by = fma2(ep0, p0b.y, by);  by = fma2(ep1, p1b.y, by);
    }
}

// ---------------------------------------------------------------------------
// k1: WARP-PER-B, zero barriers, zero smem. Each warp streams its 48
// neighbors in 24 groups of 2 with unnormalized softmax accumulation.
// nan_to_num dropped (numerically a no-op on finite inputs).
// __launch_bounds__(256,3) caps regs at 80 -> 24 warps/SM.
// ---------------------------------------------------------------------------
__global__ __launch_bounds__(256, 3) void k1(
    const float* __restrict__ embeds,
    const float* __restrict__ w_self,
    const float* __restrict__ w_nb,
    const float* __restrict__ w_nb2,
    const int*   __restrict__ idx,
    const int*   __restrict__ labels,
    const int*   __restrict__ nbr1,
    const int*   __restrict__ nbr2,
    const int    B)
{
    const int gw   = (blockIdx.x * blockDim.x + threadIdx.x) >> 5;
    const int lane = threadIdx.x & 31;
    if (gw >= B) return;
    const int b = gw;
    const unsigned FULL = 0xffffffffu;

    // ---- center (scaled by w_self) + its norm ----
    const int crow = idx[b];
    const int lab  = labels[b];
    const ulonglong2* ce = (const ulonglong2*)(embeds + (size_t)crow * H);
    const ulonglong2 sa = ((const ulonglong2*)w_self)[lane];
    const ulonglong2 sb = ((const ulonglong2*)w_self)[32 + lane];
    ulonglong2 cpa, cpb;
    {
        const ulonglong2 cea = ce[lane];
        const ulonglong2 ceb = ce[32 + lane];
        cpa.x = mul2(cea.x, sa.x);  cpa.y = mul2(cea.y, sa.y);
        cpb.x = mul2(ceb.x, sb.x);  cpb.y = mul2(ceb.y, sb.y);
    }
    float cnsq = hsum2(fma2(cpa.x, cpa.x, fma2(cpa.y, cpa.y,
                       fma2(cpb.x, cpb.x, mul2(cpb.y, cpb.y)))));
    #pragma unroll
    for (int o = 16; o; o >>= 1) cnsq += __shfl_xor_sync(FULL, cnsq, o);
    const float rcn = 1.f / fmaxf(sqrtf(cnsq), EPSF);

    // ---- stream both hops ----
    u64 ax = 0, ay = 0, bx = 0, by = 0;     // 0ULL == packed (+0,+0)
    float den = 0.f;
    {
        const ulonglong2 wa = ((const ulonglong2*)w_nb)[lane];
        const ulonglong2 wb = ((const ulonglong2*)w_nb)[32 + lane];
        hop_accum(embeds, nbr1 + b * K1, K1, wa, wb, cpa, cpb, rcn, lane,
                  ax, ay, bx, by, den);
    }
    {
        const ulonglong2 wa = ((const ulonglong2*)w_nb2)[lane];
        const ulonglong2 wb = ((const ulonglong2*)w_nb2)[32 + lane];
        hop_accum(embeds, nbr2 + b * K2, K2, wa, wb, cpa, cpb, rcn, lane,
                  ax, ay, bx, by, den);
    }

    // ---- epilogue: rawret = acc/den + center_scaled ----
    const float invd = 1.f / den;
    const u64 invd2 = pk2(invd, invd);
    ulonglong2 oa, ob;
    oa.x = fma2(ax, invd2, cpa.x);  oa.y = fma2(ay, invd2, cpa.y);
    ob.x = fma2(bx, invd2, cpb.x);  ob.y = fma2(by, invd2, cpb.y);

    u64* rr = (u64*)(g_rawret + (size_t)b * H);
    asm volatile("st.global.cs.v2.u64 [%0], {%1, %2};"
                 :: "l"(rr + 2 * lane), "l"(oa.x), "l"(oa.y) : "memory");
    asm volatile("st.global.cs.v2.u64 [%0], {%1, %2};"
                 :: "l"(rr + 64 + 2 * lane), "l"(ob.x), "l"(ob.y) : "memory");

    float* cs = g_classSums + lab * H;
    {
        float2 f;
        f = upk2(oa.x); atomicAdd(cs + 4 * lane,     f.x);
                        atomicAdd(cs + 4 * lane + 1, f.y);
        f = upk2(oa.y); atomicAdd(cs + 4 * lane + 2, f.x);
                        atomicAdd(cs + 4 * lane + 3, f.y);
        f = upk2(ob.x); atomicAdd(cs + 128 + 4 * lane,     f.x);
                        atomicAdd(cs + 128 + 4 * lane + 1, f.y);
        f = upk2(ob.y); atomicAdd(cs + 128 + 4 * lane + 2, f.x);
                        atomicAdd(cs + 128 + 4 * lane + 3, f.y);
    }
    if (lane == 0) atomicAdd(&g_counts[lab], 1);
}

// ---------------------------------------------------------------------------
// k2: ave = sums / max(cnt,1); store ave / max(||ave||, eps); reset sums/cnt.
// ---------------------------------------------------------------------------
__global__ __launch_bounds__(256) void k2()
{
    __shared__ float red[8];
    __shared__ float scnt[NC];
    const int t = threadIdx.x, lane = t & 31, w = t >> 5;

    if (t < NC) { scnt[t] = (float)g_counts[t]; g_counts[t] = 0; }
    __syncthreads();

    for (int c = 0; c < NC; c++) {
        const float s = g_classSums[c * H + t];
        g_classSums[c * H + t] = 0.f;                 // reset for next replay
        const float a = s / fmaxf(scnt[c], 1.f);

        float p = a * a;
        #pragma unroll
        for (int o = 16; o; o >>= 1) p += __shfl_xor_sync(0xffffffffu, p, o);
        if (lane == 0) red[w] = p;
        __syncthreads();
        float nsq = 0.f;
        #pragma unroll
        for (int j = 0; j < 8; j++) nsq += red[j];
        g_avescaled[c * H + t] = a / fmaxf(sqrtf(nsq), EPSF);
        __syncthreads();
    }
}

// ---------------------------------------------------------------------------
// k3: one warp per row. 7 dots + ||rawret||^2 in one 8-value butterfly,
//     then softmax over 7 classes.
// ---------------------------------------------------------------------------
__global__ __launch_bounds__(256) void k3(float* __restrict__ out, int B)
{
    const int gw   = (blockIdx.x * 256 + threadIdx.x) >> 5;
    const int lane = threadIdx.x & 31;
    if (gw >= B) return;

    const float4* rr = (const float4*)(g_rawret + (size_t)gw * H);
    const float4 r0 = rr[lane];
    const float4 r1 = rr[32 + lane];

    float v[8];
    v[7] = d4(r0, r0) + d4(r1, r1);
    #pragma unroll
    for (int c = 0; c < NC; c++) {
        const float4* av = (const float4*)(g_avescaled + c * H);
        v[c] = d4(r0, av[lane]) + d4(r1, av[32 + lane]);
    }
    #pragma unroll
    for (int o = 16; o; o >>= 1)
        #pragma unroll
        for (int j = 0; j < 8; j++)
            v[j] += __shfl_xor_sync(0xffffffffu, v[j], o);

    const float rn = fmaxf(sqrtf(v[7]), EPSF);
    float ret[NC];
    float m = -1e30f;
    #pragma unroll
    for (int c = 0; c < NC; c++) { ret[c] = v[c] / rn; m = fmaxf(m, ret[c]); }
    float s = 0.f;
    #pragma unroll
    for (int c = 0; c < NC; c++) { ret[c] = __expf(ret[c] - m); s += ret[c]; }
    if (lane < NC) out[gw * NC + lane] = ret[lane] / s;
}

extern "C" void kernel_launch(void* const* d_in, const int* in_sizes, int n_in,
                              void* d_out, int out_size)
{
    const float* embeds = (const float*)d_in[0];
    const float* w_self = (const float*)d_in[1];
    const float* w_nb   = (const float*)d_in[2];
    const float* w_nb2  = (const float*)d_in[3];
    const int*   idx    = (const int*)d_in[4];
    const int*   labels = (const int*)d_in[5];
    const int*   nbr1   = (const int*)d_in[6];
    const int*   nbr2   = (const int*)d_in[7];

    const int B = in_sizes[4];  // idx element count

    k1<<<(B + 7) / 8, 256>>>(embeds, w_self, w_nb, w_nb2, idx, labels,
                             nbr1, nbr2, B);
    k2<<<1, 256>>>();
    k3<<<(B + 7) / 8, 256>>>((float*)d_out, B);
}

// round 13
// speedup vs baseline: 1.1767x; 1.1767x over previous
#include <cuda_runtime.h>
#include <math.h>

#define H   256
#define K1  16
#define K2  32
#define KK  48
#define NC  7
#define NW  12          // warps per CTA
#define NPW 4           // neighbors per warp (NW*NPW == KK); warps 0-3 hop1
#define MAXB 14000
#define EPSF 1e-8f
#define GRIDK1 296      // 2 CTAs/SM x 148 SMs, persistent

typedef unsigned long long u64;

// Scratch (allocation-free rule: device globals). Zero-initialized at load;
// k2 restores g_classSums/g_counts to zero each launch so graph replays are
// self-consistent.
__device__ float g_rawret[(size_t)MAXB * H];
__device__ float g_classSums[NC * H];
__device__ int   g_counts[NC];
__device__ float g_avescaled[NC * H];

// ---- packed f32x2 helpers (ptxas won't emit FFMA2 from C++) ----
__device__ __forceinline__ u64 fma2(u64 a, u64 b, u64 c) {
    u64 d;
    asm("fma.rn.f32x2 %0, %1, %2, %3;" : "=l"(d) : "l"(a), "l"(b), "l"(c));
    return d;
}
__device__ __forceinline__ u64 mul2(u64 a, u64 b) {
    u64 d;
    asm("mul.rn.f32x2 %0, %1, %2;" : "=l"(d) : "l"(a), "l"(b));
    return d;
}
__device__ __forceinline__ u64 add2(u64 a, u64 b) {
    u64 d;
    asm("add.rn.f32x2 %0, %1, %2;" : "=l"(d) : "l"(a), "l"(b));
    return d;
}
__device__ __forceinline__ u64 pk2(float lo, float hi) {
    u64 r;
    asm("mov.b64 %0, {%1, %2};" : "=l"(r) : "f"(lo), "f"(hi));
    return r;
}
__device__ __forceinline__ float2 upk2(u64 v) {
    float2 r;
    asm("mov.b64 {%0, %1}, %2;" : "=f"(r.x), "=f"(r.y) : "l"(v));
    return r;
}
__device__ __forceinline__ float hsum2(u64 v) {
    const float2 f = upk2(v);
    return f.x + f.y;
}

__device__ __forceinline__ float d4(float4 a, float4 b) {
    return a.x * b.x + a.y * b.y + a.z * b.z + a.w * b.w;
}

// ---------------------------------------------------------------------------
// k1: EXACT R10 structure (persistent, one barrier/iter, f32x2 packed math,
// single-level prefetch with indices loaded mid-body) — the only change vs
// the 119.3us champion is the f32x2 packed tail (threads t < H/2 reduce
// column pairs).
// ---------------------------------------------------------------------------
__global__ __launch_bounds__(384, 2) void k1(
    const float* __restrict__ embeds,
    const float* __restrict__ w_self,
    const float* __restrict__ w_nb,
    const float* __restrict__ w_nb2,
    const int*   __restrict__ idx,
    const int*   __restrict__ labels,
    const int*   __restrict__ nbr1,
    const int*   __restrict__ nbr2,
    const int    B)
{
    __shared__ __align__(16) float part[2][NW][H];   // 24 KB
    __shared__ __align__(16) float csh[2][H];        //  2 KB
    __shared__ __align__(16) float pe[2][NW + 4];    // partial denominators

    const int t    = threadIdx.x;
    const int lane = t & 31;
    const int w    = t >> 5;
    const unsigned FULL = 0xffffffffu;

    // ---- loop-invariant packed weights ----
    const ulonglong2* wsf = (const ulonglong2*)w_self;
    const ulonglong2 sa = wsf[lane];
    const ulonglong2 sb = wsf[32 + lane];
    const ulonglong2* wsrc = (w < K1 / NPW) ? (const ulonglong2*)w_nb
                                            : (const ulonglong2*)w_nb2;
    const ulonglong2 wa = wsrc[lane];
    const ulonglong2 wb = wsrc[32 + lane];

    int b = blockIdx.x;
    if (b >= B) return;

    // ---- prefetch for first iteration ----
    ulonglong2 va[NPW], vb[NPW];
    ulonglong2 cea, ceb;
    int lab;
    {
        #pragma unroll
        for (int i = 0; i < NPW; i++) {
            const int k = w * NPW + i;
            const int row = (k < K1) ? nbr1[b * K1 + k]
                                     : nbr2[b * K2 + (k - K1)];
            const ulonglong2* vr = (const ulonglong2*)(embeds + (size_t)row * H);
            va[i] = vr[lane];
            vb[i] = vr[32 + lane];
        }
        const int crow = idx[b];
        const ulonglong2* ce = (const ulonglong2*)(embeds + (size_t)crow * H);
        cea = ce[lane];
        ceb = ce[32 + lane];
        lab = labels[b];
    }

    int parity = 0;
    while (true) {
        // ---- center (scaled); every warp computes cn (identical, no dep) ----
        ulonglong2 cpa, cpb;
        cpa.x = mul2(cea.x, sa.x);  cpa.y = mul2(cea.y, sa.y);
        cpb.x = mul2(ceb.x, sb.x);  cpb.y = mul2(ceb.y, sb.y);
        if (w == 0) {
            ((ulonglong2*)csh[parity])[lane]      = cpa;
            ((ulonglong2*)csh[parity])[32 + lane] = cpb;
        }
        float cnsq = hsum2(fma2(cpa.x, cpa.x,
                           fma2(cpa.y, cpa.y,
                           fma2(cpb.x, cpb.x, mul2(cpb.y, cpb.y)))));
        #pragma unroll
        for (int o = 16; o; o >>= 1) cnsq += __shfl_xor_sync(FULL, cnsq, o);
        const float rcn = 1.f / fmaxf(sqrtf(cnsq), EPSF);

        // ---- per-neighbor weighted dot d / weighted sq-norm q (packed) ----
        float val[2 * NPW];                    // {d0,q0,d1,q1,d2,q2,d3,q3}
        #pragma unroll
        for (int i = 0; i < NPW; i++) {
            const u64 wax = mul2(va[i].x, wa.x);
            const u64 way = mul2(va[i].y, wa.y);
            const u64 wbx = mul2(vb[i].x, wb.x);
            const u64 wby = mul2(vb[i].y, wb.y);
            val[2 * i]     = hsum2(fma2(cpa.x, wax,
                                   fma2(cpa.y, way,
                                   fma2(cpb.x, wbx, mul2(cpb.y, wby)))));
            val[2 * i + 1] = hsum2(fma2(wax, wax,
                                   fma2(way, way,
                                   fma2(wbx, wbx, mul2(wby, wby)))));
        }

        // ---- interleaved folding butterfly (8 values, 10 SHFL) ----
        // result: lane 2i holds D_i, lane 2i+1 holds Q_i (i = 0..3)
        float r[4];
        #pragma unroll
        for (int j = 0; j < 4; j++) {
            const float send = (lane & 1) ? val[2 * j] : val[2 * j + 1];
            const float recv = __shfl_xor_sync(FULL, send, 1);
            const float keep = (lane & 1) ? val[2 * j + 1] : val[2 * j];
            r[j] = keep + recv;
        }
        float u[2];
        #pragma unroll
        for (int j = 0; j < 2; j++) {
            const float send = (lane & 2) ? r[2 * j] : r[2 * j + 1];
            const float recv = __shfl_xor_sync(FULL, send, 2);
            const float keep = (lane & 2) ? r[2 * j + 1] : r[2 * j];
            u[j] = keep + recv;
        }
        float ek[NPW];
        {
            const float send = (lane & 4) ? u[0] : u[1];
            const float recv = __shfl_xor_sync(FULL, send, 4);
            const float keep = (lane & 4) ? u[1] : u[0];
            float s = keep + recv;
            s += __shfl_xor_sync(FULL, s, 8);
            s += __shfl_xor_sync(FULL, s, 16);
            const float qn = __shfl_xor_sync(FULL, s, 1);
            // on lanes 0,2,4,6: s = D_i, qn = Q_i -> unnormalized softmax term
            const float e = __expf(s * rcn / fmaxf(sqrtf(qn), EPSF));
            #pragma unroll
            for (int i = 0; i < NPW; i++)
                ek[i] = __shfl_sync(FULL, e, 2 * i);
        }
        if (lane == 0)
            pe[parity][w] = ek[0] + ek[1] + ek[2] + ek[3];

        // ---- unnormalized weighted accumulation (LAST use of va/vb) ----
        u64 aax = 0, aay = 0, abx = 0, aby = 0;   // 0ULL == packed (+0,+0)
        #pragma unroll
        for (int i = 0; i < NPW; i++) {
            const u64 ekp = pk2(ek[i], ek[i]);
            aax = fma2(ekp, va[i].x, aax);
            aay = fma2(ekp, va[i].y, aay);
            abx = fma2(ekp, vb[i].x, abx);
            aby = fma2(ekp, vb[i].y, aby);
        }

        // ---- prefetch next iteration (long overlap before next use) ----
        const int bcur = b;
        const int lcur = lab;
        const int bn = b + GRIDK1;
        const bool more = bn < B;
        if (more) {
            #pragma unroll
            for (int i = 0; i < NPW; i++) {
                const int k = w * NPW + i;
                const int row = (k < K1) ? nbr1[bn * K1 + k]
                                         : nbr2[bn * K2 + (k - K1)];
                const ulonglong2* vr =
                    (const ulonglong2*)(embeds + (size_t)row * H);
                va[i] = vr[lane];
                vb[i] = vr[32 + lane];
            }
            const int crow = idx[bn];
            const ulonglong2* ce =
                (const ulonglong2*)(embeds + (size_t)crow * H);
            cea = ce[lane];
            ceb = ce[32 + lane];
            lab = labels[bn];
        }

        // ---- partial row (hop-scaled, still unnormalized) ----
        {
            ulonglong2 pa, pb;
            pa.x = mul2(aax, wa.x);  pa.y = mul2(aay, wa.y);
            pb.x = mul2(abx, wb.x);  pb.y = mul2(aby, wb.y);
            ((ulonglong2*)part[parity][w])[lane]      = pa;
            ((ulonglong2*)part[parity][w])[32 + lane] = pb;
        }
        __syncthreads();                               // the ONE barrier

        // ---- tail in f32x2: threads t<128 handle column pairs ----
        if (t < H / 2) {
            float den = 0.f;
            #pragma unroll
            for (int r2 = 0; r2 < NW; r2++) den += pe[parity][r2];
            const float invd = 1.f / den;
            const u64 invd2 = pk2(invd, invd);

            u64 acc2 = 0;
            #pragma unroll
            for (int r2 = 0; r2 < NW; r2++)
                acc2 = add2(acc2, ((const u64*)part[parity][r2])[t]);
            const u64 rv2 = fma2(acc2, invd2, ((const u64*)csh[parity])[t]);

            __stcs((u64*)(g_rawret + (size_t)bcur * H) + t, rv2);
            const float2 rf = upk2(rv2);
            atomicAdd(&g_classSums[lcur * H + 2 * t],     rf.x);
            atomicAdd(&g_classSums[lcur * H + 2 * t + 1], rf.y);
            if (t == 0) atomicAdd(&g_counts[lcur], 1);
        }

        if (!more) break;
        b = bn;
        parity ^= 1;
    }
}

// ---------------------------------------------------------------------------
// k2: ave = sums / max(cnt,1); store ave / max(||ave||, eps); reset sums/cnt.
// ---------------------------------------------------------------------------
__global__ __launch_bounds__(256) void k2()
{
    __shared__ float red[8];
    __shared__ float scnt[NC];
    const int t = threadIdx.x, lane = t & 31, w = t >> 5;

    if (t < NC) { scnt[t] = (float)g_counts[t]; g_counts[t] = 0; }
    __syncthreads();

    for (int c = 0; c < NC; c++) {
        const float s = g_classSums[c * H + t];
        g_classSums[c * H + t] = 0.f;                 // reset for next replay
        const float a = s / fmaxf(scnt[c], 1.f);

        float p = a * a;
        #pragma unroll
        for (int o = 16; o; o >>= 1) p += __shfl_xor_sync(0xffffffffu, p, o);
        if (lane == 0) red[w] = p;
        __syncthreads();
        float nsq = 0.f;
        #pragma unroll
        for (int j = 0; j < 8; j++) nsq += red[j];
        g_avescaled[c * H + t] = a / fmaxf(sqrtf(nsq), EPSF);
        __syncthreads();
    }
}

// ---------------------------------------------------------------------------
// k3: one warp per row. 7 dots + ||rawret||^2 in one 8-value butterfly,
//     then softmax over 7 classes.
// ---------------------------------------------------------------------------
__global__ __launch_bounds__(256) void k3(float* __restrict__ out, int B)
{
    const int gw   = (blockIdx.x * 256 + threadIdx.x) >> 5;
    const int lane = threadIdx.x & 31;
    if (gw >= B) return;

    const float4* rr = (const float4*)(g_rawret + (size_t)gw * H);
    const float4 r0 = rr[lane];
    const float4 r1 = rr[32 + lane];

    float v[8];
    v[7] = d4(r0, r0) + d4(r1, r1);
    #pragma unroll
    for (int c = 0; c < NC; c++) {
        const float4* av = (const float4*)(g_avescaled + c * H);
        v[c] = d4(r0, av[lane]) + d4(r1, av[32 + lane]);
    }
    #pragma unroll
    for (int o = 16; o; o >>= 1)
        #pragma unroll
        for (int j = 0; j < 8; j++)
            v[j] += __shfl_xor_sync(0xffffffffu, v[j], o);

    const float rn = fmaxf(sqrtf(v[7]), EPSF);
    float ret[NC];
    float m = -1e30f;
    #pragma unroll
    for (int c = 0; c < NC; c++) { ret[c] = v[c] / rn; m = fmaxf(m, ret[c]); }
    float s = 0.f;
    #pragma unroll
    for (int c = 0; c < NC; c++) { ret[c] = __expf(ret[c] - m); s += ret[c]; }
    if (lane < NC) out[gw * NC + lane] = ret[lane] / s;
}

extern "C" void kernel_launch(void* const* d_in, const int* in_sizes, int n_in,
                              void* d_out, int out_size)
{
    const float* embeds = (const float*)d_in[0];
    const float* w_self = (const float*)d_in[1];
    const float* w_nb   = (const float*)d_in[2];
    const float* w_nb2  = (const float*)d_in[3];
    const int*   idx    = (const int*)d_in[4];
    const int*   labels = (const int*)d_in[5];
    const int*   nbr1   = (const int*)d_in[6];
    const int*   nbr2   = (const int*)d_in[7];

    const int B = in_sizes[4];  // idx element count

    const int grid1 = (B < GRIDK1) ? B : GRIDK1;
    k1<<<grid1, NW * 32>>>(embeds, w_self, w_nb, w_nb2, idx, labels,
                           nbr1, nbr2, B);
    k2<<<1, 256>>>();
    k3<<<(B + 7) / 8, 256>>>((float*)d_out, B);
}